// round 14
// baseline (speedup 1.0000x reference)
#include <cuda_runtime.h>
#include <cstdint>

#define THREADS 256

// ---- problem constants ----
#define Cc    4
#define Tt    1000
#define FQn   1025
#define Dd    384
#define INF   128      // W*C
#define Mrows 8000     // B*T
#define KB    45

// ---- tiling ----
#define MT    256      // rows per CTA (8 warps x 32 rows)
#define DC    32       // D chunk
#define NCH   (Dd / DC)   // 12

// Band tables (disjoint frequency groups)
__constant__ int c_start[KB] = {
    0,4,9,15,22,30,39,49,60,72,85,99,114,130,147,165,184,204,225,247,
    270,294,319,345,372,400,429,459,490,522,554,586,618,650,682,714,
    746,778,810,842,874,906,938,970,1002};
__constant__ int c_width[KB] = {
    4,5,6,7,8,9,10,11,12,13,14,15,16,17,18,19,20,21,22,23,
    24,25,26,27,28,29,30,31,32,32,32,32,32,32,32,32,
    32,32,32,32,32,32,32,32,23};

__device__ __forceinline__ uint32_t f2tf(float f) {
    uint32_t r;
    asm("cvt.rna.tf32.f32 %0, %1;" : "=r"(r) : "f"(f));
    return r;
}

__device__ __forceinline__ void mma8(float* c, const uint4 a, uint32_t b0, uint32_t b1) {
    asm volatile(
        "mma.sync.aligned.m16n8k8.row.col.f32.tf32.tf32.f32 "
        "{%0,%1,%2,%3},{%4,%5,%6,%7},{%8,%9},{%0,%1,%2,%3};"
        : "+f"(c[0]), "+f"(c[1]), "+f"(c[2]), "+f"(c[3])
        : "r"(a.x), "r"(a.y), "r"(a.z), "r"(a.w), "r"(b0), "r"(b1));
}

// smem layout (u32) as constexpr of class params
template<int KTL, int NPL> struct Layout {
    static constexpr int OFF_X  = 0;
    static constexpr int SZ_X   = 16 * KTL * 128;       // 16 m-tiles x KTL k-tiles
    static constexpr int OFF_WP = OFF_X + SZ_X;
    static constexpr int SZ_WP1 = KTL * 2 * 128;        // per buffer
    static constexpr int OFF_WQ = OFF_WP + 2 * SZ_WP1;
    static constexpr int SZ_WQ1 = 4 * NPL * 128;        // per buffer
    static constexpr int OFF_H  = OFF_WQ + 2 * SZ_WQ1;
    static constexpr int SZ_H   = 16 * 4 * 128;
    static constexpr int TOTAL  = OFF_H + SZ_H;         // u32
};

// KTL = ceil(fw_max/2) K-tiles in GEMM1; NPL = ceil(fw_max/4) N-pairs in GEMM2.
// All bands in a launch satisfy fw <= 2*KTL and fw <= 4*NPL; skipped tiles are
// exact zeros (X gather pads with 0) / never-stored outputs.
template<int KTL, int NPL>
__global__ __launch_bounds__(THREADS, 1)
void bandsplit_mma(const float* __restrict__ x,
                   const float* __restrict__ w_pre,
                   const float* __restrict__ b_pre,
                   const float* __restrict__ w_post,
                   const float* __restrict__ b_post,
                   float* __restrict__ out,
                   int k0)
{
    using L = Layout<KTL, NPL>;
    extern __shared__ uint32_t sm[];
    __shared__ float bpre_sh[2][DC];
    __shared__ float bpost_sh[INF];

    const int k     = k0 + blockIdx.y;
    const int tile0 = blockIdx.x * MT;
    const int tid   = threadIdx.x;
    const int warp  = tid >> 5;
    const int lane  = tid & 31;
    const int fs    = c_start[k];
    const int fw    = c_width[k];

    for (int i = tid; i < INF; i += THREADS) bpost_sh[i] = b_post[k * INF + i];

    // ---- gather X into A-fragment layout (tf32); only k-tiles < KTL exist ----
    for (int task = warp; task < MT * Cc; task += 8) {
        const int m  = task >> 2;
        const int c  = task & 3;
        const int mg = tile0 + m;
        const int w  = lane;
        const int kt = w >> 1;
        if (kt < KTL) {                      // compile-time bound, predicated store
            float v = 0.0f;
            if (mg < Mrows && w < fw) {
                const int b = mg / Tt;
                const int t = mg - b * Tt;
                v = x[((size_t)(b * Cc + c) * Tt + t) * FQn + fs + w];
            }
            const int gm     = m >> 4;
            const int lane_s = ((m & 7) << 2) | c;
            const int reg    = ((w & 1) << 1) | ((m >> 3) & 1);
            sm[L::OFF_X + (((gm * KTL + kt) * 32 + lane_s) << 2) + reg] = f2tf(v);
        }
    }

    // ---- register prefetch of weight chunks ----
    float wp_r[KTL], wq_r[2 * NPL], bp_r;

    auto ldg_chunk = [&](int ch) {
        const int dbase = ch * DC;
        #pragma unroll
        for (int j = 0; j < KTL; ++j) {           // w_pre: KTL*8 rows x 32 cols
            const int i  = j * THREADS + tid;
            const int kk = i >> 5;
            const int d  = i & 31;
            wp_r[j] = w_pre[((size_t)k * INF + kk) * Dd + dbase + d];
        }
        #pragma unroll
        for (int j = 0; j < 2 * NPL; ++j) {       // w_post: 32 rows x NPL*16 cols
            const int i = j * THREADS + tid;
            const int d = i / (NPL * 16);
            const int o = i - d * (NPL * 16);
            wq_r[j] = w_post[((size_t)k * Dd + dbase + d) * INF + o];
        }
        bp_r = (tid < DC) ? b_pre[k * Dd + dbase + tid] : 0.0f;
    };

    auto sts_chunk = [&](int bsel) {
        uint32_t* WP = sm + L::OFF_WP + bsel * L::SZ_WP1;
        uint32_t* WQ = sm + L::OFF_WQ + bsel * L::SZ_WQ1;
        #pragma unroll
        for (int j = 0; j < KTL; ++j) {
            const int i  = j * THREADS + tid;
            const int kk = i >> 5;
            const int d  = i & 31;
            const int kt = kk >> 3, kr = kk & 7, nt = d >> 3, nc = d & 7;
            const int np = nt >> 1, p = nt & 1;
            const int lane_s = (nc << 2) | (kr & 3);
            const int reg    = (p << 1) | (kr >> 2);
            WP[(((kt * 2 + np) * 32 + lane_s) << 2) + reg] = f2tf(wp_r[j]);
        }
        #pragma unroll
        for (int j = 0; j < 2 * NPL; ++j) {
            const int i = j * THREADS + tid;
            const int d = i / (NPL * 16);
            const int o = i - d * (NPL * 16);
            const int kt = d >> 3, kr = d & 7, nt = o >> 3, nc = o & 7;
            const int np = nt >> 1, p = nt & 1;
            const int lane_s = (nc << 2) | (kr & 3);
            const int reg    = (p << 1) | (kr >> 2);
            // stride must match GEMM2 consumer: (kt * NPL + np)
            WQ[(((kt * NPL + np) * 32 + lane_s) << 2) + reg] = f2tf(wq_r[j]);
        }
        if (tid < DC) bpre_sh[bsel][tid] = bp_r;
    };

    // GEMM2 accumulators: 2 m-tiles x 2*NPL n-tiles x 4 regs (static indexing)
    float yacc[2][2 * NPL][4];
    #pragma unroll
    for (int mt = 0; mt < 2; ++mt)
        #pragma unroll
        for (int nt = 0; nt < 2 * NPL; ++nt)
            #pragma unroll
            for (int e = 0; e < 4; ++e) yacc[mt][nt][e] = 0.0f;

    ldg_chunk(0);
    sts_chunk(0);
    __syncthreads();

    int buf = 0;
    for (int ch = 0; ch < NCH; ++ch) {
        if (ch + 1 < NCH) ldg_chunk(ch + 1);   // LDG issued; first use after GEMM2

        const uint32_t* WP = sm + L::OFF_WP + buf * L::SZ_WP1;
        const uint32_t* WQ = sm + L::OFF_WQ + buf * L::SZ_WQ1;

        // ---- GEMM1: H[32 x DC] per warp, K = KTL*8 ----
        float h[2][4][4];
        #pragma unroll
        for (int mt = 0; mt < 2; ++mt)
            #pragma unroll
            for (int nt = 0; nt < 4; ++nt)
                #pragma unroll
                for (int e = 0; e < 4; ++e) h[mt][nt][e] = 0.0f;

        {
            const uint4* XF  = (const uint4*)(sm + L::OFF_X);
            const uint4* WpF = (const uint4*)WP;
            #pragma unroll
            for (int kt = 0; kt < KTL; ++kt) {
                const uint4 a0 = XF[((warp * 2 + 0) * KTL + kt) * 32 + lane];
                const uint4 a1 = XF[((warp * 2 + 1) * KTL + kt) * 32 + lane];
                #pragma unroll
                for (int np = 0; np < 2; ++np) {
                    const uint4 b = WpF[(kt * 2 + np) * 32 + lane];
                    mma8(h[0][np * 2],     a0, b.x, b.y);
                    mma8(h[1][np * 2],     a1, b.x, b.y);
                    mma8(h[0][np * 2 + 1], a0, b.z, b.w);
                    mma8(h[1][np * 2 + 1], a1, b.z, b.w);
                }
            }
        }

        // ---- repack H (+b_pre, tf32) into GEMM2 A-fragment layout (warp-private) ----
        #pragma unroll
        for (int e = 0; e < 4; ++e) {
            const int lane2 = (lane & 0x1C) | ((lane & 1) << 1) | (e & 1);
            const int reg2  = (((lane >> 1) & 1) << 1) | (e >> 1);
            const int col   = ((lane & 3) << 1) | (e & 1);
            #pragma unroll
            for (int mt = 0; mt < 2; ++mt)
                #pragma unroll
                for (int nt = 0; nt < 4; ++nt) {   // D dense: 4 k-tiles always
                    const int d = nt * 8 + col;
                    const float v = h[mt][nt][e] + bpre_sh[buf][d];
                    sm[L::OFF_H + ((((warp * 2 + mt) * 4 + nt) * 32 + lane2) << 2) + reg2] = f2tf(v);
                }
        }
        __syncwarp();

        // ---- GEMM2: Y[32 x NPL*16] += H[32 x DC] * Wpost ----
        {
            const uint4* HF  = (const uint4*)(sm + L::OFF_H);
            const uint4* WqF = (const uint4*)WQ;
            #pragma unroll
            for (int kt = 0; kt < 4; ++kt) {
                const uint4 a0 = HF[((warp * 2 + 0) * 4 + kt) * 32 + lane];
                const uint4 a1 = HF[((warp * 2 + 1) * 4 + kt) * 32 + lane];
                #pragma unroll
                for (int np = 0; np < NPL; ++np) {
                    const uint4 b = WqF[(kt * NPL + np) * 32 + lane];
                    mma8(yacc[0][np * 2],     a0, b.x, b.y);
                    mma8(yacc[1][np * 2],     a1, b.x, b.y);
                    mma8(yacc[0][np * 2 + 1], a0, b.z, b.w);
                    mma8(yacc[1][np * 2 + 1], a1, b.z, b.w);
                }
            }
        }

        if (ch + 1 < NCH) sts_chunk(buf ^ 1);
        __syncthreads();
        buf ^= 1;
    }

    // ---- epilogue: stage Y in smem (reuse front region), then coalesced scatter ----
    // Ybuf [m][c][w], w < 2*KTL: c-stride 2*KTL+1, m-stride 4*(2*KTL+1)
    constexpr int CST = 2 * KTL + 1;
    float* Ybuf = (float*)sm;
    #pragma unroll
    for (int e = 0; e < 4; ++e) {
        const int r   = (lane >> 2) + ((e >> 1) << 3);
        const int col = ((lane & 3) << 1) | (e & 1);
        #pragma unroll
        for (int mt = 0; mt < 2; ++mt) {
            const int m = warp * 32 + mt * 16 + r;
            #pragma unroll
            for (int nt = 0; nt < 2 * NPL; ++nt) {
                const int o = nt * 8 + col;
                const int w = o >> 2;
                if (w < 2 * KTL)   // compile-time shape guard
                    Ybuf[m * 4 * CST + (o & 3) * CST + w] = yacc[mt][nt][e] + bpost_sh[o];
            }
        }
    }
    __syncthreads();

    for (int task = warp; task < MT * Cc; task += 8) {
        const int m  = task >> 2;
        const int c  = task & 3;
        const int mg = tile0 + m;
        const int w  = lane;
        if (mg < Mrows && w < fw) {
            const int b = mg / Tt;
            const int t = mg - b * Tt;
            out[((size_t)(b * Cc + c) * Tt + t) * FQn + fs + w] = Ybuf[m * 4 * CST + c * CST + w];
        }
    }
}

template<int KTL, int NPL>
static void launch_class(const float* x, const float* w_pre, const float* b_pre,
                         const float* w_post, const float* b_post, float* out,
                         int k0, int nbands)
{
    constexpr size_t smem_bytes = (size_t)Layout<KTL, NPL>::TOTAL * sizeof(uint32_t);
    cudaFuncSetAttribute(bandsplit_mma<KTL, NPL>,
                         cudaFuncAttributeMaxDynamicSharedMemorySize,
                         (int)smem_bytes);
    dim3 grid((Mrows + MT - 1) / MT, nbands);
    bandsplit_mma<KTL, NPL><<<grid, THREADS, smem_bytes>>>(
        x, w_pre, b_pre, w_post, b_post, out, k0);
}

extern "C" void kernel_launch(void* const* d_in, const int* in_sizes, int n_in,
                              void* d_out, int out_size)
{
    (void)in_sizes; (void)n_in; (void)out_size;
    const float* x      = (const float*)d_in[0];
    const float* w_pre  = (const float*)d_in[1];
    const float* b_pre  = (const float*)d_in[2];
    const float* w_post = (const float*)d_in[3];
    const float* b_post = (const float*)d_in[4];
    float* out = (float*)d_out;

    // classes by band width (bands contiguous per class); largest first
    launch_class<16, 8>(x, w_pre, b_pre, w_post, b_post, out, 21, 23);  // fw 25..32
    launch_class<12, 6>(x, w_pre, b_pre, w_post, b_post, out, 13,  8);  // fw 17..24
    launch_class<12, 6>(x, w_pre, b_pre, w_post, b_post, out, 44,  1);  // fw 23
    launch_class< 8, 4>(x, w_pre, b_pre, w_post, b_post, out,  5,  8);  // fw 9..16
    launch_class< 4, 2>(x, w_pre, b_pre, w_post, b_post, out,  0,  5);  // fw 4..8
}

// round 15
// speedup vs baseline: 1.2050x; 1.2050x over previous
#include <cuda_runtime.h>
#include <cstdint>

#define THREADS 256

// ---- problem constants ----
#define Cc    4
#define Tt    1000
#define FQn   1025
#define Dd    384
#define INF   128      // W*C
#define Mrows 8000     // B*T
#define KB    45

// ---- tiling ----
#define MT    256      // rows per CTA (8 warps x 32 rows)
#define DC    32       // D chunk
#define NCH   (Dd / DC)   // 12

// Band tables (disjoint frequency groups)
__constant__ int c_start[KB] = {
    0,4,9,15,22,30,39,49,60,72,85,99,114,130,147,165,184,204,225,247,
    270,294,319,345,372,400,429,459,490,522,554,586,618,650,682,714,
    746,778,810,842,874,906,938,970,1002};
__constant__ int c_width[KB] = {
    4,5,6,7,8,9,10,11,12,13,14,15,16,17,18,19,20,21,22,23,
    24,25,26,27,28,29,30,31,32,32,32,32,32,32,32,32,
    32,32,32,32,32,32,32,32,23};

__device__ __forceinline__ uint32_t f2tf(float f) {
    uint32_t r;
    asm("cvt.rna.tf32.f32 %0, %1;" : "=r"(r) : "f"(f));
    return r;
}

__device__ __forceinline__ void mma8(float* c, const uint4 a, uint32_t b0, uint32_t b1) {
    asm volatile(
        "mma.sync.aligned.m16n8k8.row.col.f32.tf32.tf32.f32 "
        "{%0,%1,%2,%3},{%4,%5,%6,%7},{%8,%9},{%0,%1,%2,%3};"
        : "+f"(c[0]), "+f"(c[1]), "+f"(c[2]), "+f"(c[3])
        : "r"(a.x), "r"(a.y), "r"(a.z), "r"(a.w), "r"(b0), "r"(b1));
}

// smem layout (u32) as constexpr of class params
template<int KTL, int NPL> struct Layout {
    static constexpr int OFF_X  = 0;
    static constexpr int SZ_X   = 16 * KTL * 128;       // 16 m-tiles x KTL k-tiles
    static constexpr int OFF_WP = OFF_X + SZ_X;
    static constexpr int SZ_WP1 = KTL * 2 * 128;        // per buffer
    static constexpr int OFF_WQ = OFF_WP + 2 * SZ_WP1;
    static constexpr int SZ_WQ1 = 4 * NPL * 128;        // per buffer
    static constexpr int OFF_H  = OFF_WQ + 2 * SZ_WQ1;
    static constexpr int SZ_H   = 16 * 4 * 128;
    static constexpr int TOTAL  = OFF_H + SZ_H;         // u32
};

// One band's full pipeline, compile-time shaped by its width class.
// KTL = ceil(fw_max/2) GEMM1 K-tiles; NPL = ceil(fw_max/4) GEMM2 N-pairs.
// fw <= 2*KTL and fw <= 4*NPL for every band dispatched here; skipped tiles
// are exact zeros (X gather pads) / never-stored outputs -> bit-identical.
template<int KTL, int NPL>
__device__ __forceinline__ void band_body(
    const float* __restrict__ x,
    const float* __restrict__ w_pre,
    const float* __restrict__ b_pre,
    const float* __restrict__ w_post,
    const float* __restrict__ b_post,
    float* __restrict__ out,
    uint32_t* sm, float (&bpre_sh)[2][DC], float (&bpost_sh)[INF],
    int k, int tile0, int tid, int warp, int lane, int fs, int fw)
{
    using L = Layout<KTL, NPL>;

    for (int i = tid; i < INF; i += THREADS) bpost_sh[i] = b_post[k * INF + i];

    // ---- gather X into A-fragment layout (tf32); only k-tiles < KTL exist ----
    for (int task = warp; task < MT * Cc; task += 8) {
        const int m  = task >> 2;
        const int c  = task & 3;
        const int mg = tile0 + m;
        const int w  = lane;
        const int kt = w >> 1;
        if (kt < KTL) {
            float v = 0.0f;
            if (mg < Mrows && w < fw) {
                const int b = mg / Tt;
                const int t = mg - b * Tt;
                v = x[((size_t)(b * Cc + c) * Tt + t) * FQn + fs + w];
            }
            const int gm     = m >> 4;
            const int lane_s = ((m & 7) << 2) | c;
            const int reg    = ((w & 1) << 1) | ((m >> 3) & 1);
            sm[L::OFF_X + (((gm * KTL + kt) * 32 + lane_s) << 2) + reg] = f2tf(v);
        }
    }

    // ---- register prefetch of weight chunks ----
    float wp_r[KTL], wq_r[2 * NPL], bp_r;

    auto ldg_chunk = [&](int ch) {
        const int dbase = ch * DC;
        #pragma unroll
        for (int j = 0; j < KTL; ++j) {           // w_pre: KTL*8 rows x 32 cols
            const int i  = j * THREADS + tid;
            const int kk = i >> 5;
            const int d  = i & 31;
            wp_r[j] = w_pre[((size_t)k * INF + kk) * Dd + dbase + d];
        }
        #pragma unroll
        for (int j = 0; j < 2 * NPL; ++j) {       // w_post: 32 rows x NPL*16 cols
            const int i = j * THREADS + tid;
            const int d = i / (NPL * 16);
            const int o = i - d * (NPL * 16);
            wq_r[j] = w_post[((size_t)k * Dd + dbase + d) * INF + o];
        }
        bp_r = (tid < DC) ? b_pre[k * Dd + dbase + tid] : 0.0f;
    };

    auto sts_chunk = [&](int bsel) {
        uint32_t* WP = sm + L::OFF_WP + bsel * L::SZ_WP1;
        uint32_t* WQ = sm + L::OFF_WQ + bsel * L::SZ_WQ1;
        #pragma unroll
        for (int j = 0; j < KTL; ++j) {
            const int i  = j * THREADS + tid;
            const int kk = i >> 5;
            const int d  = i & 31;
            const int kt = kk >> 3, kr = kk & 7, nt = d >> 3, nc = d & 7;
            const int np = nt >> 1, p = nt & 1;
            const int lane_s = (nc << 2) | (kr & 3);
            const int reg    = (p << 1) | (kr >> 2);
            WP[(((kt * 2 + np) * 32 + lane_s) << 2) + reg] = f2tf(wp_r[j]);
        }
        #pragma unroll
        for (int j = 0; j < 2 * NPL; ++j) {
            const int i = j * THREADS + tid;
            const int d = i / (NPL * 16);
            const int o = i - d * (NPL * 16);
            const int kt = d >> 3, kr = d & 7, nt = o >> 3, nc = o & 7;
            const int np = nt >> 1, p = nt & 1;
            const int lane_s = (nc << 2) | (kr & 3);
            const int reg    = (p << 1) | (kr >> 2);
            // stride matches GEMM2 consumer: (kt * NPL + np)
            WQ[(((kt * NPL + np) * 32 + lane_s) << 2) + reg] = f2tf(wq_r[j]);
        }
        if (tid < DC) bpre_sh[bsel][tid] = bp_r;
    };

    // GEMM2 accumulators: 2 m-tiles x 2*NPL n-tiles x 4 regs (static indexing)
    float yacc[2][2 * NPL][4];
    #pragma unroll
    for (int mt = 0; mt < 2; ++mt)
        #pragma unroll
        for (int nt = 0; nt < 2 * NPL; ++nt)
            #pragma unroll
            for (int e = 0; e < 4; ++e) yacc[mt][nt][e] = 0.0f;

    ldg_chunk(0);
    sts_chunk(0);
    __syncthreads();

    int buf = 0;
    for (int ch = 0; ch < NCH; ++ch) {
        if (ch + 1 < NCH) ldg_chunk(ch + 1);   // LDG issued; first use after GEMM2

        const uint32_t* WP = sm + L::OFF_WP + buf * L::SZ_WP1;
        const uint32_t* WQ = sm + L::OFF_WQ + buf * L::SZ_WQ1;

        // ---- GEMM1: H[32 x DC] per warp, K = KTL*8 ----
        float h[2][4][4];
        #pragma unroll
        for (int mt = 0; mt < 2; ++mt)
            #pragma unroll
            for (int nt = 0; nt < 4; ++nt)
                #pragma unroll
                for (int e = 0; e < 4; ++e) h[mt][nt][e] = 0.0f;

        {
            const uint4* XF  = (const uint4*)(sm + L::OFF_X);
            const uint4* WpF = (const uint4*)WP;
            #pragma unroll
            for (int kt = 0; kt < KTL; ++kt) {
                const uint4 a0 = XF[((warp * 2 + 0) * KTL + kt) * 32 + lane];
                const uint4 a1 = XF[((warp * 2 + 1) * KTL + kt) * 32 + lane];
                #pragma unroll
                for (int np = 0; np < 2; ++np) {
                    const uint4 b = WpF[(kt * 2 + np) * 32 + lane];
                    mma8(h[0][np * 2],     a0, b.x, b.y);
                    mma8(h[1][np * 2],     a1, b.x, b.y);
                    mma8(h[0][np * 2 + 1], a0, b.z, b.w);
                    mma8(h[1][np * 2 + 1], a1, b.z, b.w);
                }
            }
        }

        // ---- repack H (+b_pre, tf32) into GEMM2 A-fragment layout (warp-private) ----
        #pragma unroll
        for (int e = 0; e < 4; ++e) {
            const int lane2 = (lane & 0x1C) | ((lane & 1) << 1) | (e & 1);
            const int reg2  = (((lane >> 1) & 1) << 1) | (e >> 1);
            const int col   = ((lane & 3) << 1) | (e & 1);
            #pragma unroll
            for (int mt = 0; mt < 2; ++mt)
                #pragma unroll
                for (int nt = 0; nt < 4; ++nt) {   // D dense: 4 k-tiles always
                    const int d = nt * 8 + col;
                    const float v = h[mt][nt][e] + bpre_sh[buf][d];
                    sm[L::OFF_H + ((((warp * 2 + mt) * 4 + nt) * 32 + lane2) << 2) + reg2] = f2tf(v);
                }
        }
        __syncwarp();

        // ---- GEMM2: Y[32 x NPL*16] += H[32 x DC] * Wpost ----
        {
            const uint4* HF  = (const uint4*)(sm + L::OFF_H);
            const uint4* WqF = (const uint4*)WQ;
            #pragma unroll
            for (int kt = 0; kt < 4; ++kt) {
                const uint4 a0 = HF[((warp * 2 + 0) * 4 + kt) * 32 + lane];
                const uint4 a1 = HF[((warp * 2 + 1) * 4 + kt) * 32 + lane];
                #pragma unroll
                for (int np = 0; np < NPL; ++np) {
                    const uint4 b = WqF[(kt * NPL + np) * 32 + lane];
                    mma8(yacc[0][np * 2],     a0, b.x, b.y);
                    mma8(yacc[1][np * 2],     a1, b.x, b.y);
                    mma8(yacc[0][np * 2 + 1], a0, b.z, b.w);
                    mma8(yacc[1][np * 2 + 1], a1, b.z, b.w);
                }
            }
        }

        if (ch + 1 < NCH) sts_chunk(buf ^ 1);
        __syncthreads();
        buf ^= 1;
    }

    // ---- epilogue: stage Y in smem (reuse front region), then coalesced scatter ----
    constexpr int CST = 2 * KTL + 1;
    float* Ybuf = (float*)sm;
    #pragma unroll
    for (int e = 0; e < 4; ++e) {
        const int r   = (lane >> 2) + ((e >> 1) << 3);
        const int col = ((lane & 3) << 1) | (e & 1);
        #pragma unroll
        for (int mt = 0; mt < 2; ++mt) {
            const int m = warp * 32 + mt * 16 + r;
            #pragma unroll
            for (int nt = 0; nt < 2 * NPL; ++nt) {
                const int o = nt * 8 + col;
                const int w = o >> 2;
                if (w < 2 * KTL)   // compile-time shape guard
                    Ybuf[m * 4 * CST + (o & 3) * CST + w] = yacc[mt][nt][e] + bpost_sh[o];
            }
        }
    }
    __syncthreads();

    for (int task = warp; task < MT * Cc; task += 8) {
        const int m  = task >> 2;
        const int c  = task & 3;
        const int mg = tile0 + m;
        const int w  = lane;
        if (mg < Mrows && w < fw) {
            const int b = mg / Tt;
            const int t = mg - b * Tt;
            out[((size_t)(b * Cc + c) * Tt + t) * FQn + fs + w] = Ybuf[m * 4 * CST + c * CST + w];
        }
    }
}

// Single launch; per-CTA class dispatch on band index (uniform, no divergence).
__global__ __launch_bounds__(THREADS, 1)
void bandsplit_all(const float* __restrict__ x,
                   const float* __restrict__ w_pre,
                   const float* __restrict__ b_pre,
                   const float* __restrict__ w_post,
                   const float* __restrict__ b_post,
                   float* __restrict__ out)
{
    extern __shared__ uint32_t sm[];
    __shared__ float bpre_sh[2][DC];
    __shared__ float bpost_sh[INF];

    const int k     = blockIdx.y;
    const int tile0 = blockIdx.x * MT;
    const int tid   = threadIdx.x;
    const int warp  = tid >> 5;
    const int lane  = tid & 31;
    const int fs    = c_start[k];
    const int fw    = c_width[k];

    if (k >= 21 && k <= 43) {            // fw 25..32
        band_body<16, 8>(x, w_pre, b_pre, w_post, b_post, out,
                         sm, bpre_sh, bpost_sh, k, tile0, tid, warp, lane, fs, fw);
    } else if (k >= 13) {                // fw 17..24  (k 13..20 and k==44)
        band_body<12, 6>(x, w_pre, b_pre, w_post, b_post, out,
                         sm, bpre_sh, bpost_sh, k, tile0, tid, warp, lane, fs, fw);
    } else if (k >= 5) {                 // fw 9..16
        band_body<8, 4>(x, w_pre, b_pre, w_post, b_post, out,
                        sm, bpre_sh, bpost_sh, k, tile0, tid, warp, lane, fs, fw);
    } else {                             // fw 4..8
        band_body<4, 2>(x, w_pre, b_pre, w_post, b_post, out,
                        sm, bpre_sh, bpost_sh, k, tile0, tid, warp, lane, fs, fw);
    }
}

extern "C" void kernel_launch(void* const* d_in, const int* in_sizes, int n_in,
                              void* d_out, int out_size)
{
    (void)in_sizes; (void)n_in; (void)out_size;
    const float* x      = (const float*)d_in[0];
    const float* w_pre  = (const float*)d_in[1];
    const float* b_pre  = (const float*)d_in[2];
    const float* w_post = (const float*)d_in[3];
    const float* b_post = (const float*)d_in[4];
    float* out = (float*)d_out;

    constexpr size_t smem_bytes = (size_t)Layout<16, 8>::TOTAL * sizeof(uint32_t); // 224 KB
    cudaFuncSetAttribute(bandsplit_all,
                         cudaFuncAttributeMaxDynamicSharedMemorySize,
                         (int)smem_bytes);

    dim3 grid((Mrows + MT - 1) / MT, KB);   // (32, 45) — one full-chip launch
    bandsplit_all<<<grid, THREADS, smem_bytes>>>(x, w_pre, b_pre, w_post, b_post, out);
}

// round 17
// speedup vs baseline: 1.2106x; 1.0046x over previous
#include <cuda_runtime.h>
#include <cstdint>

#define THREADS 384
#define NW      12      // warps per CTA; warp == m-tile index

// ---- problem constants ----
#define Cc    4
#define Tt    1000
#define FQn   1025
#define Dd    384
#define INF   128      // W*C
#define Mrows 8000     // B*T
#define KB    45

// ---- tiling ----
#define MT    192      // rows per CTA (12 warps x 16 rows)
#define NMT   (MT/16)  // 12 m-tiles
#define DC    32       // D chunk
#define NCH   (Dd / DC)   // 12

// ---- smem layout (uint32 units), MMA fragment order, weights double-buffered ----
#define OFF_X   0
#define SZ_X    (NMT*16*128)    // 24576 : 12 m-tiles x 16 k-tiles
#define OFF_WP  (OFF_X + SZ_X)
#define SZ_WP1  (16*2*128)      // 4096 per buffer
#define OFF_WQ  (OFF_WP + 2*SZ_WP1)
#define SZ_WQ1  (4*8*128)       // 4096 per buffer
#define OFF_H   (OFF_WQ + 2*SZ_WQ1)
#define SZ_H    (NMT*4*128)     // 6144
#define SMEM_U32 (OFF_H + SZ_H) // 47104 u32 = 184 KB

// Band tables (disjoint frequency groups)
__constant__ int c_start[KB] = {
    0,4,9,15,22,30,39,49,60,72,85,99,114,130,147,165,184,204,225,247,
    270,294,319,345,372,400,429,459,490,522,554,586,618,650,682,714,
    746,778,810,842,874,906,938,970,1002};
__constant__ int c_width[KB] = {
    4,5,6,7,8,9,10,11,12,13,14,15,16,17,18,19,20,21,22,23,
    24,25,26,27,28,29,30,31,32,32,32,32,32,32,32,32,
    32,32,32,32,32,32,32,32,23};

__device__ __forceinline__ uint32_t f2tf(float f) {
    uint32_t r;
    asm("cvt.rna.tf32.f32 %0, %1;" : "=r"(r) : "f"(f));
    return r;
}

__device__ __forceinline__ void mma8(float* c, const uint4 a, uint32_t b0, uint32_t b1) {
    asm volatile(
        "mma.sync.aligned.m16n8k8.row.col.f32.tf32.tf32.f32 "
        "{%0,%1,%2,%3},{%4,%5,%6,%7},{%8,%9},{%0,%1,%2,%3};"
        : "+f"(c[0]), "+f"(c[1]), "+f"(c[2]), "+f"(c[3])
        : "r"(a.x), "r"(a.y), "r"(a.z), "r"(a.w), "r"(b0), "r"(b1));
}

__global__ __launch_bounds__(THREADS, 1)
void bandsplit_mma(const float* __restrict__ x,
                   const float* __restrict__ w_pre,
                   const float* __restrict__ b_pre,
                   const float* __restrict__ w_post,
                   const float* __restrict__ b_post,
                   float* __restrict__ out)
{
    extern __shared__ uint32_t sm[];
    __shared__ float bpre_sh[2][DC];
    __shared__ float bpost_sh[INF];

    const int k     = blockIdx.y;
    const int tile0 = blockIdx.x * MT;
    const int tid   = threadIdx.x;
    const int warp  = tid >> 5;      // 0..11, == m-tile index
    const int lane  = tid & 31;
    const int fs    = c_start[k];
    const int fw    = c_width[k];

    for (int i = tid; i < INF; i += THREADS) bpost_sh[i] = b_post[k * INF + i];

    // ---- gather X into A-fragment layout (tf32) ----
    // one warp per (m, channel): lanes read consecutive freqs (coalesced 128B)
    for (int task = warp; task < MT * Cc; task += NW) {
        const int m  = task >> 2;
        const int c  = task & 3;
        const int mg = tile0 + m;
        const int w  = lane;
        float v = 0.0f;
        if (mg < Mrows && w < fw) {
            const int b = mg / Tt;
            const int t = mg - b * Tt;
            v = x[((size_t)(b * Cc + c) * Tt + t) * FQn + fs + w];
        }
        const int kt     = w >> 1;
        const int gm     = m >> 4;   // 0..11
        const int lane_s = ((m & 7) << 2) | c;
        const int reg    = ((w & 1) << 1) | ((m >> 3) & 1);
        sm[OFF_X + (((gm * 16 + kt) * 32 + lane_s) << 2) + reg] = f2tf(v);
    }

    // ---- register prefetch of weight chunks (4096 floats over 384 threads: 11 slots) ----
    float wp_r[11], wq_r[11], bp_r;

    auto ldg_chunk = [&](int ch) {
        const int dbase = ch * DC;
        #pragma unroll
        for (int j = 0; j < 11; ++j) {            // w_pre: 128 rows x 32 cols
            const int i = j * THREADS + tid;
            if (j < 10 || i < 128 * DC) {
                const int kk = i >> 5;
                const int d  = i & 31;
                wp_r[j] = w_pre[((size_t)k * INF + kk) * Dd + dbase + d];
            }
        }
        #pragma unroll
        for (int j = 0; j < 11; ++j) {            // w_post: 32 rows x 128 cols
            const int i = j * THREADS + tid;
            if (j < 10 || i < DC * INF) {
                const int d = i >> 7;
                const int o = i & 127;
                wq_r[j] = w_post[((size_t)k * Dd + dbase + d) * INF + o];
            }
        }
        bp_r = (tid < DC) ? b_pre[k * Dd + dbase + tid] : 0.0f;
    };

    auto sts_chunk = [&](int bsel) {
        uint32_t* WP = sm + OFF_WP + bsel * SZ_WP1;
        uint32_t* WQ = sm + OFF_WQ + bsel * SZ_WQ1;
        #pragma unroll
        for (int j = 0; j < 11; ++j) {
            const int i = j * THREADS + tid;
            if (j < 10 || i < 128 * DC) {
                const int kk = i >> 5;
                const int d  = i & 31;
                const int kt = kk >> 3, kr = kk & 7, nt = d >> 3, nc = d & 7;
                const int np = nt >> 1, p = nt & 1;
                const int lane_s = (nc << 2) | (kr & 3);
                const int reg    = (p << 1) | (kr >> 2);
                WP[(((kt * 2 + np) * 32 + lane_s) << 2) + reg] = f2tf(wp_r[j]);
            }
        }
        #pragma unroll
        for (int j = 0; j < 11; ++j) {
            const int i = j * THREADS + tid;
            if (j < 10 || i < DC * INF) {
                const int d = i >> 7;
                const int o = i & 127;
                const int kt = d >> 3, kr = d & 7, nt = o >> 3, nc = o & 7;
                const int np = nt >> 1, p = nt & 1;
                const int lane_s = (nc << 2) | (kr & 3);
                const int reg    = (p << 1) | (kr >> 2);
                WQ[(((kt * 8 + np) * 32 + lane_s) << 2) + reg] = f2tf(wq_r[j]);
            }
        }
        if (tid < DC) bpre_sh[bsel][tid] = bp_r;
    };

    // GEMM2 accumulators: 16 n-tiles x 4 regs (1 m-tile per warp)
    float yacc[16][4];
    #pragma unroll
    for (int nt = 0; nt < 16; ++nt)
        #pragma unroll
        for (int e = 0; e < 4; ++e) yacc[nt][e] = 0.0f;

    // prologue: stage chunk 0; barrier also covers X gather
    ldg_chunk(0);
    sts_chunk(0);
    __syncthreads();

    int buf = 0;
    for (int ch = 0; ch < NCH; ++ch) {
        // issue next chunk's LDGs now; first use (STS) is after GEMM2
        if (ch + 1 < NCH) ldg_chunk(ch + 1);

        const uint32_t* WP = sm + OFF_WP + buf * SZ_WP1;
        const uint32_t* WQ = sm + OFF_WQ + buf * SZ_WQ1;

        // ---- GEMM1: H[16 x DC] per warp, K = 128 ----
        float h[4][4];
        #pragma unroll
        for (int nt = 0; nt < 4; ++nt)
            #pragma unroll
            for (int e = 0; e < 4; ++e) h[nt][e] = 0.0f;

        {
            const uint4* XF  = (const uint4*)(sm + OFF_X);
            const uint4* WpF = (const uint4*)WP;
            #pragma unroll
            for (int kt = 0; kt < 16; ++kt) {
                const uint4 a = XF[(warp * 16 + kt) * 32 + lane];
                #pragma unroll
                for (int np = 0; np < 2; ++np) {
                    const uint4 b = WpF[(kt * 2 + np) * 32 + lane];
                    mma8(h[np * 2],     a, b.x, b.y);
                    mma8(h[np * 2 + 1], a, b.z, b.w);
                }
            }
        }

        // ---- repack H (+b_pre, tf32) into GEMM2 A-fragment layout (warp-private) ----
        #pragma unroll
        for (int e = 0; e < 4; ++e) {
            const int lane2 = (lane & 0x1C) | ((lane & 1) << 1) | (e & 1);
            const int reg2  = (((lane >> 1) & 1) << 1) | (e >> 1);
            const int col   = ((lane & 3) << 1) | (e & 1);
            #pragma unroll
            for (int nt = 0; nt < 4; ++nt) {   // D dense: 4 k-tiles of GEMM2
                const int d = nt * 8 + col;
                const float v = h[nt][e] + bpre_sh[buf][d];
                sm[OFF_H + (((warp * 4 + nt) * 32 + lane2) << 2) + reg2] = f2tf(v);
            }
        }
        __syncwarp();

        // ---- GEMM2: Y[16 x 128] += H[16 x DC] * Wpost[DC x 128] ----
        {
            const uint4* HF  = (const uint4*)(sm + OFF_H);
            const uint4* WqF = (const uint4*)WQ;
            #pragma unroll
            for (int kt = 0; kt < 4; ++kt) {
                const uint4 a = HF[(warp * 4 + kt) * 32 + lane];
                #pragma unroll
                for (int np = 0; np < 8; ++np) {
                    const uint4 b = WqF[(kt * 8 + np) * 32 + lane];
                    mma8(yacc[np * 2],     a, b.x, b.y);
                    mma8(yacc[np * 2 + 1], a, b.z, b.w);
                }
            }
        }

        // store prefetched chunk into the other buffer, then ONE barrier
        if (ch + 1 < NCH) sts_chunk(buf ^ 1);
        __syncthreads();
        buf ^= 1;
    }

    // ---- epilogue: stage Y in smem (reuse front region), then coalesced scatter ----
    float* Ybuf = (float*)sm;   // [m][c][w] : m stride 132, c stride 33 (25344 <= 47104)
    #pragma unroll
    for (int e = 0; e < 4; ++e) {
        const int r   = (lane >> 2) + ((e >> 1) << 3);
        const int col = ((lane & 3) << 1) | (e & 1);
        const int m   = warp * 16 + r;
        #pragma unroll
        for (int nt = 0; nt < 16; ++nt) {
            const int o = nt * 8 + col;
            Ybuf[m * 132 + (o & 3) * 33 + (o >> 2)] = yacc[nt][e] + bpost_sh[o];
        }
    }
    __syncthreads();

    for (int task = warp; task < MT * Cc; task += NW) {
        const int m  = task >> 2;
        const int c  = task & 3;
        const int mg = tile0 + m;
        const int w  = lane;
        if (mg < Mrows && w < fw) {
            const int b = mg / Tt;
            const int t = mg - b * Tt;
            out[((size_t)(b * Cc + c) * Tt + t) * FQn + fs + w] = Ybuf[m * 132 + c * 33 + w];
        }
    }
}

extern "C" void kernel_launch(void* const* d_in, const int* in_sizes, int n_in,
                              void* d_out, int out_size)
{
    (void)in_sizes; (void)n_in; (void)out_size;
    const float* x      = (const float*)d_in[0];
    const float* w_pre  = (const float*)d_in[1];
    const float* b_pre  = (const float*)d_in[2];
    const float* w_post = (const float*)d_in[3];
    const float* b_post = (const float*)d_in[4];
    float* out = (float*)d_out;

    const size_t smem_bytes = (size_t)SMEM_U32 * sizeof(uint32_t);  // 184 KB
    cudaFuncSetAttribute(bandsplit_mma,
                         cudaFuncAttributeMaxDynamicSharedMemorySize,
                         (int)smem_bytes);

    dim3 grid((Mrows + MT - 1) / MT, KB);   // (42, 45)
    bandsplit_mma<<<grid, THREADS, smem_bytes>>>(x, w_pre, b_pre, w_post, b_post, out);
}